// round 9
// baseline (speedup 1.0000x reference)
#include <cuda_runtime.h>

// Problem constants
#define B_    16
#define CIN   8
#define COUT  32
#define DIN   48
#define DOUT  46
#define WSTR  40      // w_s n stride (32 + 8 pad, conflict-free)
#define KPP   56      // k-slots per ic-pair (54 real + 2 pad)
#define NCH   7       // k8 chunks per ic-pair
#define TPB   128     // 4 warps

// x_s tile: [ic 8][kd 3][hh 10][ww 18]
#define XW    18
#define XH    (10 * XW)     // 180
#define XICL  (3 * XH)      // 540  (per single ic)
#define XSZ   (CIN * XICL)  // 4320

// smem word offsets
#define SO_W    0
#define WSZ     (4 * KPP * WSTR)      // 8960
#define SO_X    WSZ                   // 8960
#define SO_B    (SO_X + XSZ)          // 13280
#define SO_RED  (SO_B + 32)           // 13312
#define SMEM_WORDS (SO_RED + 64)      // 13376 -> 53504 bytes

#define NPOS_F (46.f * 46.f * 46.f)
#define EPSGN  1e-5f

__device__ float    g_sums[B_ * 64];
__device__ unsigned g_wB[WSZ];   // tf32 bits [icpair][56][40]

__device__ __forceinline__ unsigned f2tf32(float f) {
    unsigned u; asm("cvt.rna.tf32.f32 %0, %1;" : "=r"(u) : "f"(f)); return u;
}

__device__ __forceinline__ void mma_tf32(float* c, const unsigned* a, const unsigned* b) {
    asm volatile(
        "mma.sync.aligned.m16n8k8.row.col.f32.tf32.tf32.f32 "
        "{%0,%1,%2,%3}, {%4,%5,%6,%7}, {%8,%9}, {%0,%1,%2,%3};"
        : "+f"(c[0]), "+f"(c[1]), "+f"(c[2]), "+f"(c[3])
        : "r"(a[0]), "r"(a[1]), "r"(a[2]), "r"(a[3]), "r"(b[0]), "r"(b[1]));
}

// ---------------------------------------------------------------------------
// Prep: zero accumulators + padded tf32 weights [icpair][j:56][n:40]
// ---------------------------------------------------------------------------
__global__ void prep_kernel(const float* __restrict__ w)
{
    int t = threadIdx.x;
    if (t < B_ * 64) g_sums[t] = 0.f;
    for (int i = t; i < WSZ; i += 1024) {
        int n = i % WSTR;
        int r = i / WSTR;
        int j = r % KPP;
        int p = r / KPP;
        unsigned val = 0u;
        if (j < 54 && n < COUT) {
            int icl = j / 27, tap = j - 27 * icl;
            int ic  = 2 * p + icl;
            int kd = tap / 9, r2 = tap - 9 * kd;
            int kh = r2 / 3, kw = r2 - 3 * kh;
            val = f2tf32(w[(((n * CIN + ic) * 3 + kd) * 3 + kh) * 3 + kw]);
        }
        g_wB[i] = val;
    }
}

// ---------------------------------------------------------------------------
// Implicit-GEMM conv3d (tf32 mma.sync), small CTA for occupancy 4
// grid = (18 = 6 h-chunks x 3 w-tiles, 46 d, 16 b), block = 128
// Warp w: output rows {2w, 2w+1} x 16 w-cols; M=32 (2 m-tiles), N=32, K=224
// ---------------------------------------------------------------------------
extern __shared__ unsigned smem_u[];

__global__ void __launch_bounds__(TPB)
conv_mma_kernel(const float* __restrict__ x, const float* __restrict__ bias)
{
    unsigned* w_s = smem_u + SO_W;
    unsigned* x_s = smem_u + SO_X;
    float* b_s    = (float*)(smem_u + SO_B);
    float* s_red  = (float*)(smem_u + SO_RED);

    const int bx  = blockIdx.x;
    const int hc  = bx % 6, wt = bx / 6;
    const int h0  = hc * 8, w0g = wt * 16;
    const int d0  = blockIdx.y, b = blockIdx.z;
    const int tid = threadIdx.x;

    // --- weights: coalesced float4 copy (2240 uint4) ---
    {
        const uint4* src = (const uint4*)g_wB;
        uint4* dst = (uint4*)w_s;
        for (int i = tid; i < WSZ / 4; i += TPB) dst[i] = src[i];
    }
    if (tid < 64) s_red[tid] = 0.f;
    if (tid < COUT) b_s[tid] = bias[tid];

    // --- x tile: [8 ic][3 kd][10 h][18 w], tf32, zero halo ---
    for (int i = tid; i < XSZ; i += TPB) {
        int col = i % XW;
        int r   = i / XW;
        int hh  = r % 10;
        int r2  = r / 10;
        int kd  = r2 % 3;
        int ic  = r2 / 3;
        int hg  = h0 + hh, wg = w0g + col;
        float v = 0.f;
        if (hg < DIN && wg < DIN)
            v = x[(((b * CIN + ic) * DIN + d0 + kd) * DIN + hg) * DIN + wg];
        x_s[i] = f2tf32(v);
    }
    __syncthreads();

    const int wid = tid >> 5, lane = tid & 31;
    const int grp = lane >> 2, c = lane & 3;

    // im2col offsets: chunk cc covers k-slots j = 8cc + c (+4)
    int roff[NCH][2];
    #pragma unroll
    for (int cc = 0; cc < NCH; cc++) {
        #pragma unroll
        for (int s = 0; s < 2; s++) {
            int jj = 8 * cc + c + 4 * s;
            int o = 0;
            if (jj < 54) {
                int icl = jj / 27, tap = jj - 27 * icl;
                int kd = tap / 9, r2 = tap - 9 * kd;
                int kh = r2 / 3, kw = r2 - 3 * kh;
                o = icl * XICL + kd * XH + kh * XW + kw;
            }
            roff[cc][s] = o;
        }
    }

    float acc[2][4][4];
    #pragma unroll
    for (int m = 0; m < 2; m++)
        #pragma unroll
        for (int n = 0; n < 4; n++)
            #pragma unroll
            for (int k = 0; k < 4; k++) acc[m][n][k] = 0.f;

    const int xbase = (2 * wid) * XW + grp;    // mt adds +XW (next row)

    #pragma unroll 1
    for (int p = 0; p < 4; p++) {
        const int xb = xbase + p * (2 * XICL);     // ic-pair base (1080)
        const int wb = p * (KPP * WSTR) + c * WSTR + grp;
        #pragma unroll
        for (int cc = 0; cc < NCH; cc++) {
            unsigned bf[4][2];
            #pragma unroll
            for (int nt = 0; nt < 4; nt++) {
                bf[nt][0] = w_s[wb + (8 * cc)     * WSTR + nt * 8];
                bf[nt][1] = w_s[wb + (8 * cc + 4) * WSTR + nt * 8];
            }
            const int A1 = xb + roff[cc][0];
            const int A2 = xb + roff[cc][1];
            unsigned af[2][4];
            #pragma unroll
            for (int mt = 0; mt < 2; mt++) {
                const int o = mt * XW;
                af[mt][0] = x_s[A1 + o];
                af[mt][1] = x_s[A1 + o + 8];
                af[mt][2] = x_s[A2 + o];
                af[mt][3] = x_s[A2 + o + 8];
            }
            #pragma unroll
            for (int mt = 0; mt < 2; mt++)
                #pragma unroll
                for (int nt = 0; nt < 4; nt++)
                    mma_tf32(acc[mt][nt], af[mt], bf[nt]);
        }
    }

    // --- bias + hardswish + masked channel sums ---
    const bool vh[2] = { (h0 + 2 * wid) < DOUT, (h0 + 2 * wid + 1) < DOUT };
    const bool vw[2] = { (w0g + grp) < DOUT, (w0g + grp + 8) < DOUT };

    float sv[8], s2[8];
    #pragma unroll
    for (int i = 0; i < 8; i++) { sv[i] = 0.f; s2[i] = 0.f; }

    #pragma unroll
    for (int mt = 0; mt < 2; mt++) {
        #pragma unroll
        for (int half = 0; half < 2; half++) {
            const bool valid = vh[mt] && vw[half];
            #pragma unroll
            for (int nt = 0; nt < 4; nt++) {
                #pragma unroll
                for (int pr = 0; pr < 2; pr++) {
                    int ch = nt * 8 + 2 * c + pr;
                    float y = acc[mt][nt][half * 2 + pr] + b_s[ch];
                    float t = fminf(fmaxf(y + 3.f, 0.f), 6.f);
                    float v = valid ? y * t * (1.f / 6.f) : 0.f;
                    sv[nt * 2 + pr] += v;
                    s2[nt * 2 + pr] += v * v;
                }
            }
        }
    }

    // reduce across the 8 lanes sharing c: xor 4, 8, 16
    #pragma unroll
    for (int i = 0; i < 8; i++) {
        #pragma unroll
        for (int off = 4; off <= 16; off <<= 1) {
            sv[i] += __shfl_xor_sync(0xffffffffu, sv[i], off);
            s2[i] += __shfl_xor_sync(0xffffffffu, s2[i], off);
        }
    }
    if (grp == 0) {
        #pragma unroll
        for (int i = 0; i < 8; i++) {
            int ch = (i >> 1) * 8 + 2 * c + (i & 1);
            atomicAdd(&s_red[ch],      sv[i]);
            atomicAdd(&s_red[32 + ch], s2[i]);
        }
    }
    __syncthreads();
    if (tid < 64) atomicAdd(&g_sums[b * 64 + tid], s_red[tid]);
}

// ---------------------------------------------------------------------------
// Finalize: GroupNorm stats from channel sums -> [B, C]
// ---------------------------------------------------------------------------
__global__ void finalize_kernel(const float* __restrict__ gn_w,
                                const float* __restrict__ gn_b,
                                float* __restrict__ out)
{
    int i = threadIdx.x;
    if (i >= B_ * COUT) return;
    int b = i >> 5, c = i & 31;
    int g = c >> 3;
    const float* s = &g_sums[b * 64];
    float S1 = 0.f, S2 = 0.f;
    #pragma unroll
    for (int j = 0; j < 8; j++) {
        S1 += s[g * 8 + j];
        S2 += s[32 + g * 8 + j];
    }
    float invNg = 1.f / (8.f * NPOS_F);
    float mean  = S1 * invNg;
    float var   = S2 * invNg - mean * mean;
    float rinv  = rsqrtf(var + EPSGN);
    float mc    = s[c] * (1.f / NPOS_F);
    out[i] = (mc - mean) * rinv * gn_w[c] + gn_b[c];
}

// ---------------------------------------------------------------------------
extern "C" void kernel_launch(void* const* d_in, const int* in_sizes, int n_in,
                              void* d_out, int out_size)
{
    const float* x      = (const float*)d_in[0];
    const float* weight = (const float*)d_in[1];
    const float* bias   = (const float*)d_in[2];
    const float* gn_w   = (const float*)d_in[3];
    const float* gn_b   = (const float*)d_in[4];
    float* out = (float*)d_out;

    const int smem_bytes = SMEM_WORDS * 4;   // 53504
    cudaFuncSetAttribute(conv_mma_kernel,
                         cudaFuncAttributeMaxDynamicSharedMemorySize, smem_bytes);

    prep_kernel<<<1, 1024>>>(weight);

    dim3 grid(18, DOUT, B_);   // (6 h-chunks x 3 w-tiles, 46 d, 16 b)
    conv_mma_kernel<<<grid, TPB, smem_bytes>>>(x, bias);

    finalize_kernel<<<1, 512>>>(gn_w, gn_b, out);
}

// round 10
// speedup vs baseline: 2.9049x; 2.9049x over previous
#include <cuda_runtime.h>
#include <cuda_fp16.h>

// Problem constants
#define B_    16
#define CIN   8
#define COUT  32
#define DIN   48
#define DOUT  46
#define TPB   384     // 12 warps: 4 row-pairs x 3 w-tiles (R7 chassis)
#define NPAIR 144     // 8 ic x 9 (kd,kh) x 2 kw-pairs
#define NCHK  18      // 144 pairs / 8 per k16 chunk
#define WSTR  40      // w2_s pair stride in b32 (32 + 8 pad, conflict-free)

// x2 tile: [ic 8][plane 4][hh 10][col 50] packed half2 sliding pairs
#define XCW   50
#define XPL   (10 * XCW)      // 500
#define XIC2  (4 * XPL)       // 2000
#define X2SZ  (CIN * XIC2)    // 16000

// smem word offsets
#define SO_X2   0
#define SO_W    X2SZ                   // 16000
#define WSZ     (NPAIR * WSTR)         // 5760
#define SO_ROFF (SO_W + WSZ)           // 21760
#define SO_B    (SO_ROFF + NPAIR)      // 21904
#define SO_RED  (SO_B + 32)            // 21936
#define SMEM_WORDS (SO_RED + 64)       // 22000 -> 88000 bytes

#define NPOS_F (46.f * 46.f * 46.f)
#define EPSGN  1e-5f

__device__ float    g_sums[B_ * 64];
__device__ unsigned g_w2[WSZ];   // packed half2 weights [pair][40]

__device__ __forceinline__ unsigned packh2(float a, float b) {
    __half2 h = __floats2half2_rn(a, b);   // lo=a, hi=b
    return *(unsigned*)&h;
}

__device__ __forceinline__ void mma_f16(float* c, const unsigned* a, const unsigned* b) {
    asm volatile(
        "mma.sync.aligned.m16n8k16.row.col.f32.f16.f16.f32 "
        "{%0,%1,%2,%3}, {%4,%5,%6,%7}, {%8,%9}, {%0,%1,%2,%3};"
        : "+f"(c[0]), "+f"(c[1]), "+f"(c[2]), "+f"(c[3])
        : "r"(a[0]), "r"(a[1]), "r"(a[2]), "r"(a[3]), "r"(b[0]), "r"(b[1]));
}

// ---------------------------------------------------------------------------
// Prep: zero accumulators + packed-pair fp16 weights [pair:144][n:40]
// pair p: ic=p/18, rem=p%18, (kd,kh)=rem/2, t=rem%2 -> taps kw={2t, 2t+1(or 0)}
// ---------------------------------------------------------------------------
__global__ void prep_kernel(const float* __restrict__ w)
{
    int t = threadIdx.x;
    if (t < B_ * 64) g_sums[t] = 0.f;
    for (int i = t; i < WSZ; i += 1024) {
        int n = i % WSTR;
        int p = i / WSTR;
        int ic  = p / 18, rem = p % 18;
        int tap9 = rem >> 1, tp = rem & 1;
        int kd = tap9 / 3, kh = tap9 % 3;
        float wa = 0.f, wb = 0.f;
        if (n < COUT) {
            const float* base = &w[(((n * CIN + ic) * 3 + kd) * 3 + kh) * 3];
            wa = base[2 * tp];
            if (tp == 0) wb = base[1];
        }
        g_w2[i] = packh2(wa, wb);
    }
}

// ---------------------------------------------------------------------------
// Implicit-GEMM conv3d (fp16 m16n8k16), 2 d-outputs per block (R7 chassis)
// grid = (6 h-chunks, 23 d-pairs, 16 b), block = 384
// ---------------------------------------------------------------------------
extern __shared__ unsigned smem_u[];

__global__ void __launch_bounds__(TPB)
conv_mma_kernel(const float* __restrict__ x, const float* __restrict__ bias)
{
    unsigned* x2_s  = smem_u + SO_X2;
    unsigned* w2_s  = smem_u + SO_W;
    unsigned* roff_s = smem_u + SO_ROFF;
    float* b_s   = (float*)(smem_u + SO_B);
    float* s_red = (float*)(smem_u + SO_RED);

    const int b   = blockIdx.z;
    const int db  = blockIdx.y;          // d-pair: outputs 2db, 2db+1
    const int h0  = blockIdx.x * 8;
    const int tid = threadIdx.x;

    // --- weights: coalesced uint4 copy (1440 uint4) ---
    {
        const uint4* src = (const uint4*)g_w2;
        uint4* dst = (uint4*)w2_s;
        for (int i = tid; i < WSZ / 4; i += TPB) dst[i] = src[i];
    }
    // --- roff table: pair -> x2 offset ---
    if (tid < NPAIR) {
        int p = tid;
        int ic = p / 18, rem = p % 18;
        int tap9 = rem >> 1, tp = rem & 1;
        int kd = tap9 / 3, kh = tap9 % 3;
        roff_s[p] = (unsigned)(ic * XIC2 + kd * XPL + kh * XCW + 2 * tp);
    }
    if (tid < 64) s_red[tid] = 0.f;
    if (tid < COUT) b_s[tid] = bias[tid];

    // --- x2 tile: [8 ic][4 planes][10 rows][50 cols] packed pairs ---
    for (int i = tid; i < X2SZ; i += TPB) {
        int col = i % XCW;
        int r   = i / XCW;
        int hh  = r % 10;
        int r2  = r / 10;
        int kd4 = r2 & 3;
        int ic  = r2 >> 2;
        int hg  = h0 + hh;
        int dg  = 2 * db + kd4;          // <= 47, in-bounds
        float v0 = 0.f, v1 = 0.f;
        if (hg < DIN) {
            const float* row = &x[(((b * CIN + ic) * DIN + dg) * DIN + hg) * DIN];
            if (col < DIN)     v0 = row[col];
            if (col + 1 < DIN) v1 = row[col + 1];
        }
        x2_s[i] = packh2(v0, v1);
    }
    __syncthreads();

    const int wid = tid >> 5, lane = tid & 31;
    const int grp = lane >> 2, c = lane & 3;
    const int wt  = wid % 3,  hp = wid / 3;     // w-tile (16 wide), row-pair
    const int w0  = wt * 16;

    const bool vh[2] = { true, (h0 + hp + 4) < DOUT };
    const bool vw[2] = { (w0 + grp) < DOUT, (w0 + grp + 8) < DOUT };

    float sv[8], s2[8];
    #pragma unroll
    for (int i = 0; i < 8; i++) { sv[i] = 0.f; s2[i] = 0.f; }

    #pragma unroll 1
    for (int dd = 0; dd < 2; dd++) {
        float acc[2][4][4];
        #pragma unroll
        for (int m = 0; m < 2; m++)
            #pragma unroll
            for (int n = 0; n < 4; n++)
                #pragma unroll
                for (int k = 0; k < 4; k++) acc[m][n][k] = 0.f;

        const int xbase = dd * XPL + hp * XCW + w0 + grp;

        #pragma unroll 2
        for (int cc = 0; cc < NCHK; cc++) {
            const int P1 = 8 * cc + c;
            const int o1 = (int)roff_s[P1];
            const int o2 = (int)roff_s[P1 + 4];

            unsigned bf[4][2];
            #pragma unroll
            for (int nt = 0; nt < 4; nt++) {
                bf[nt][0] = w2_s[P1 * WSTR + nt * 8 + grp];
                bf[nt][1] = w2_s[(P1 + 4) * WSTR + nt * 8 + grp];
            }
            const int A1 = xbase + o1;
            const int A2 = xbase + o2;
            unsigned af[2][4];
            #pragma unroll
            for (int mt = 0; mt < 2; mt++) {
                const int o = mt * (4 * XCW);        // rows hp, hp+4
                af[mt][0] = x2_s[A1 + o];
                af[mt][1] = x2_s[A1 + o + 8];
                af[mt][2] = x2_s[A2 + o];
                af[mt][3] = x2_s[A2 + o + 8];
            }
            #pragma unroll
            for (int mt = 0; mt < 2; mt++)
                #pragma unroll
                for (int nt = 0; nt < 4; nt++)
                    mma_f16(acc[mt][nt], af[mt], bf[nt]);
        }

        // --- bias + hardswish + masked accumulate ---
        #pragma unroll
        for (int mt = 0; mt < 2; mt++) {
            #pragma unroll
            for (int half = 0; half < 2; half++) {
                const bool valid = vh[mt] && vw[half];
                #pragma unroll
                for (int nt = 0; nt < 4; nt++) {
                    #pragma unroll
                    for (int pr = 0; pr < 2; pr++) {
                        int ch = nt * 8 + 2 * c + pr;
                        float y = acc[mt][nt][half * 2 + pr] + b_s[ch];
                        float t = fminf(fmaxf(y + 3.f, 0.f), 6.f);
                        float v = valid ? y * t * (1.f / 6.f) : 0.f;
                        sv[nt * 2 + pr] += v;
                        s2[nt * 2 + pr] += v * v;
                    }
                }
            }
        }
    }

    // reduce across the 8 lanes sharing c: xor 4, 8, 16
    #pragma unroll
    for (int i = 0; i < 8; i++) {
        #pragma unroll
        for (int off = 4; off <= 16; off <<= 1) {
            sv[i] += __shfl_xor_sync(0xffffffffu, sv[i], off);
            s2[i] += __shfl_xor_sync(0xffffffffu, s2[i], off);
        }
    }
    if (grp == 0) {
        #pragma unroll
        for (int i = 0; i < 8; i++) {
            int ch = (i >> 1) * 8 + 2 * c + (i & 1);
            atomicAdd(&s_red[ch],      sv[i]);
            atomicAdd(&s_red[32 + ch], s2[i]);
        }
    }
    __syncthreads();
    if (tid < 64) atomicAdd(&g_sums[b * 64 + tid], s_red[tid]);
}

// ---------------------------------------------------------------------------
// Finalize: GroupNorm stats from channel sums -> [B, C]
// ---------------------------------------------------------------------------
__global__ void finalize_kernel(const float* __restrict__ gn_w,
                                const float* __restrict__ gn_b,
                                float* __restrict__ out)
{
    int i = threadIdx.x;
    if (i >= B_ * COUT) return;
    int b = i >> 5, c = i & 31;
    int g = c >> 3;
    const float* s = &g_sums[b * 64];
    float S1 = 0.f, S2 = 0.f;
    #pragma unroll
    for (int j = 0; j < 8; j++) {
        S1 += s[g * 8 + j];
        S2 += s[32 + g * 8 + j];
    }
    float invNg = 1.f / (8.f * NPOS_F);
    float mean  = S1 * invNg;
    float var   = S2 * invNg - mean * mean;
    float rinv  = rsqrtf(var + EPSGN);
    float mc    = s[c] * (1.f / NPOS_F);
    out[i] = (mc - mean) * rinv * gn_w[c] + gn_b[c];
}

// ---------------------------------------------------------------------------
extern "C" void kernel_launch(void* const* d_in, const int* in_sizes, int n_in,
                              void* d_out, int out_size)
{
    const float* x      = (const float*)d_in[0];
    const float* weight = (const float*)d_in[1];
    const float* bias   = (const float*)d_in[2];
    const float* gn_w   = (const float*)d_in[3];
    const float* gn_b   = (const float*)d_in[4];
    float* out = (float*)d_out;

    const int smem_bytes = SMEM_WORDS * 4;   // 88000
    cudaFuncSetAttribute(conv_mma_kernel,
                         cudaFuncAttributeMaxDynamicSharedMemorySize, smem_bytes);

    prep_kernel<<<1, 1024>>>(weight);

    dim3 grid(6, 23, B_);
    conv_mma_kernel<<<grid, TPB, smem_bytes>>>(x, bias);

    finalize_kernel<<<1, 512>>>(gn_w, gn_b, out);
}

// round 11
// speedup vs baseline: 3.4817x; 1.1986x over previous
#include <cuda_runtime.h>
#include <cuda_fp16.h>

// Problem constants
#define B_    16
#define CIN   8
#define COUT  32
#define DIN   48
#define DOUT  46
#define TPB   384     // 12 warps: 3 w-tiles x 4 h-rows
#define NPAIR 144     // 8 ic x 9 (kd,kh) x 2 kw-pairs
#define NCHK  18      // 144 / 8 per k16 chunk
#define WSTR  40      // w2_s pair stride (32 + 8 pad, conflict-free)

// x2 tile: [ic 8][plane 4][hh 6][col 50] packed half2 sliding pairs
#define XCW   50
#define XPL   (6 * XCW)       // 300 (plane stride)
#define XIC2  (4 * XPL)       // 1200
#define X2SZ  (CIN * XIC2)    // 9600

// smem word offsets
#define SO_X2   0
#define SO_W    X2SZ                   // 9600
#define WSZ     (NPAIR * WSTR)         // 5760
#define SO_ROFF (SO_W + WSZ)           // 15360
#define SO_B    (SO_ROFF + NPAIR)      // 15504
#define SO_RED  (SO_B + 32)            // 15536
#define SMEM_WORDS (SO_RED + 64)       // 15600 -> 62400 bytes

#define NPOS_F (46.f * 46.f * 46.f)
#define EPSGN  1e-5f

typedef unsigned long long u64;

__device__ float    g_sums[B_ * 64];
__device__ unsigned g_w2[WSZ];   // packed half2 weights [pair][40]

__device__ __forceinline__ unsigned packh2(float a, float b) {
    __half2 h = __floats2half2_rn(a, b);   // lo=a, hi=b
    return *(unsigned*)&h;
}

__device__ __forceinline__ void mma_f16(float* c, const unsigned* a, const unsigned* b) {
    asm volatile(
        "mma.sync.aligned.m16n8k16.row.col.f32.f16.f16.f32 "
        "{%0,%1,%2,%3}, {%4,%5,%6,%7}, {%8,%9}, {%0,%1,%2,%3};"
        : "+f"(c[0]), "+f"(c[1]), "+f"(c[2]), "+f"(c[3])
        : "r"(a[0]), "r"(a[1]), "r"(a[2]), "r"(a[3]), "r"(b[0]), "r"(b[1]));
}

// ---------------------------------------------------------------------------
// Prep: zero accumulators + packed-pair fp16 weights [pair:144][n:40]
// ---------------------------------------------------------------------------
__global__ void prep_kernel(const float* __restrict__ w)
{
    int t = threadIdx.x;
    if (t < B_ * 64) g_sums[t] = 0.f;
    for (int i = t; i < WSZ; i += 1024) {
        int n = i % WSTR;
        int p = i / WSTR;
        int ic  = p / 18, rem = p % 18;
        int tap9 = rem >> 1, tp = rem & 1;
        int kd = tap9 / 3, kh = tap9 % 3;
        float wa = 0.f, wb = 0.f;
        if (n < COUT) {
            const float* base = &w[(((n * CIN + ic) * 3 + kd) * 3 + kh) * 3];
            wa = base[2 * tp];
            if (tp == 0) wb = base[1];
        }
        g_w2[i] = packh2(wa, wb);
    }
}

// ---------------------------------------------------------------------------
// Implicit-GEMM conv3d (fp16 m16n8k16), m-subtiles = the 2 d-outputs
// grid = (12 h-chunks, 23 d-pairs, 16 b), block = 384
// Warp: 1 h-row x 16 w x 2 d x 32 ch; single K loop shares B across dd
// ---------------------------------------------------------------------------
extern __shared__ unsigned smem_u[];

__global__ void __launch_bounds__(TPB)
conv_mma_kernel(const float* __restrict__ x, const float* __restrict__ bias)
{
    unsigned* x2_s   = smem_u + SO_X2;
    unsigned* w2_s   = smem_u + SO_W;
    unsigned* roff_s = smem_u + SO_ROFF;
    float* b_s   = (float*)(smem_u + SO_B);
    float* s_red = (float*)(smem_u + SO_RED);

    const int b   = blockIdx.z;
    const int db  = blockIdx.y;          // d outputs 2db, 2db+1 (always < 46)
    const int h0  = blockIdx.x * 4;
    const int tid = threadIdx.x;

    // --- weights: coalesced uint4 copy (1440 uint4) ---
    {
        const uint4* src = (const uint4*)g_w2;
        uint4* dst = (uint4*)w2_s;
        for (int i = tid; i < WSZ / 4; i += TPB) dst[i] = src[i];
    }
    // --- roff table: pair -> x2 offset (plane = kd) ---
    if (tid < NPAIR) {
        int p = tid;
        int ic = p / 18, rem = p % 18;
        int tap9 = rem >> 1, tp = rem & 1;
        int kd = tap9 / 3, kh = tap9 % 3;
        roff_s[p] = (unsigned)(ic * XIC2 + kd * XPL + kh * XCW + 2 * tp);
    }
    if (tid < 64) s_red[tid] = 0.f;
    if (tid < COUT) b_s[tid] = bias[tid];

    // --- x2 tile: row-based load+pack. 192 rows = [ic 8][pl 4][hh 6] ---
    if (tid < CIN * 4 * 6) {
        int hh  = tid % 6;
        int r2  = tid / 6;
        int pl  = r2 & 3;
        int ic  = r2 >> 2;
        int hg  = h0 + hh;
        int dg  = 2 * db + pl;           // <= 47, in-bounds
        float xf[48];
        if (hg < DIN) {
            const float4* row = (const float4*)
                &x[(((b * CIN + ic) * DIN + dg) * DIN + hg) * DIN];
            #pragma unroll
            for (int q = 0; q < 12; q++) {
                float4 v = row[q];
                xf[4*q] = v.x; xf[4*q+1] = v.y; xf[4*q+2] = v.z; xf[4*q+3] = v.w;
            }
        } else {
            #pragma unroll
            for (int q = 0; q < 48; q++) xf[q] = 0.f;
        }
        u64* dst = (u64*)&x2_s[tid * XCW];   // word base even -> 8B aligned
        #pragma unroll
        for (int q = 0; q < 25; q++) {
            int i0 = 2 * q, i1 = 2 * q + 1;
            unsigned lo = packh2(xf[i0], (i0 + 1 < 48) ? xf[i0 + 1] : 0.f);
            unsigned hi = (i1 < 48)
                ? packh2(xf[i1], (i1 + 1 < 48) ? xf[i1 + 1] : 0.f) : 0u;
            dst[q] = (u64)lo | ((u64)hi << 32);
        }
    }
    __syncthreads();

    const int wid = tid >> 5, lane = tid & 31;
    const int grp = lane >> 2, c = lane & 3;
    const int wt  = wid % 3,  hp = wid / 3;     // w-tile (16 wide), h-row
    const int w0  = wt * 16;

    float acc[2][4][4];
    #pragma unroll
    for (int m = 0; m < 2; m++)
        #pragma unroll
        for (int n = 0; n < 4; n++)
            #pragma unroll
            for (int k = 0; k < 4; k++) acc[m][n][k] = 0.f;

    const int xbase = hp * XCW + w0 + grp;

    // ---- single K loop: B + roff loaded once, reused for both d ----
    #pragma unroll 2
    for (int cc = 0; cc < NCHK; cc++) {
        const int P1 = 8 * cc + c;
        const int o1 = (int)roff_s[P1];
        const int o2 = (int)roff_s[P1 + 4];

        unsigned bf[4][2];
        #pragma unroll
        for (int nt = 0; nt < 4; nt++) {
            bf[nt][0] = w2_s[P1 * WSTR + nt * 8 + grp];
            bf[nt][1] = w2_s[(P1 + 4) * WSTR + nt * 8 + grp];
        }
        const int A1 = xbase + o1;
        const int A2 = xbase + o2;
        #pragma unroll
        for (int dd = 0; dd < 2; dd++) {
            const int o = dd * XPL;
            unsigned af[4];
            af[0] = x2_s[A1 + o];
            af[1] = x2_s[A1 + o + 8];
            af[2] = x2_s[A2 + o];
            af[3] = x2_s[A2 + o + 8];
            #pragma unroll
            for (int nt = 0; nt < 4; nt++)
                mma_f16(acc[dd][nt], af, bf[nt]);
        }
    }

    // --- bias + hardswish + masked channel sums (d always valid) ---
    const bool vh0  = (h0 + hp) < DOUT;
    const bool vw[2] = { vh0 && (w0 + grp) < DOUT, vh0 && (w0 + grp + 8) < DOUT };

    float sv[8], s2[8];
    #pragma unroll
    for (int i = 0; i < 8; i++) { sv[i] = 0.f; s2[i] = 0.f; }

    #pragma unroll
    for (int dd = 0; dd < 2; dd++) {
        #pragma unroll
        for (int half = 0; half < 2; half++) {
            const bool valid = vw[half];
            #pragma unroll
            for (int nt = 0; nt < 4; nt++) {
                #pragma unroll
                for (int pr = 0; pr < 2; pr++) {
                    int ch = nt * 8 + 2 * c + pr;
                    float y = acc[dd][nt][half * 2 + pr] + b_s[ch];
                    float t = fminf(fmaxf(y + 3.f, 0.f), 6.f);
                    float v = valid ? y * t * (1.f / 6.f) : 0.f;
                    sv[nt * 2 + pr] += v;
                    s2[nt * 2 + pr] += v * v;
                }
            }
        }
    }

    // reduce across the 8 lanes sharing c: xor 4, 8, 16
    #pragma unroll
    for (int i = 0; i < 8; i++) {
        #pragma unroll
        for (int off = 4; off <= 16; off <<= 1) {
            sv[i] += __shfl_xor_sync(0xffffffffu, sv[i], off);
            s2[i] += __shfl_xor_sync(0xffffffffu, s2[i], off);
        }
    }
    if (grp == 0) {
        #pragma unroll
        for (int i = 0; i < 8; i++) {
            int ch = (i >> 1) * 8 + 2 * c + (i & 1);
            atomicAdd(&s_red[ch],      sv[i]);
            atomicAdd(&s_red[32 + ch], s2[i]);
        }
    }
    __syncthreads();
    if (tid < 64) atomicAdd(&g_sums[b * 64 + tid], s_red[tid]);
}

// ---------------------------------------------------------------------------
// Finalize: GroupNorm stats from channel sums -> [B, C]
// ---------------------------------------------------------------------------
__global__ void finalize_kernel(const float* __restrict__ gn_w,
                                const float* __restrict__ gn_b,
                                float* __restrict__ out)
{
    int i = threadIdx.x;
    if (i >= B_ * COUT) return;
    int b = i >> 5, c = i & 31;
    int g = c >> 3;
    const float* s = &g_sums[b * 64];
    float S1 = 0.f, S2 = 0.f;
    #pragma unroll
    for (int j = 0; j < 8; j++) {
        S1 += s[g * 8 + j];
        S2 += s[32 + g * 8 + j];
    }
    float invNg = 1.f / (8.f * NPOS_F);
    float mean  = S1 * invNg;
    float var   = S2 * invNg - mean * mean;
    float rinv  = rsqrtf(var + EPSGN);
    float mc    = s[c] * (1.f / NPOS_F);
    out[i] = (mc - mean) * rinv * gn_w[c] + gn_b[c];
}

// ---------------------------------------------------------------------------
extern "C" void kernel_launch(void* const* d_in, const int* in_sizes, int n_in,
                              void* d_out, int out_size)
{
    const float* x      = (const float*)d_in[0];
    const float* weight = (const float*)d_in[1];
    const float* bias   = (const float*)d_in[2];
    const float* gn_w   = (const float*)d_in[3];
    const float* gn_b   = (const float*)d_in[4];
    float* out = (float*)d_out;

    const int smem_bytes = SMEM_WORDS * 4;   // 62400
    cudaFuncSetAttribute(conv_mma_kernel,
                         cudaFuncAttributeMaxDynamicSharedMemorySize, smem_bytes);

    prep_kernel<<<1, 1024>>>(weight);

    dim3 grid(12, 23, B_);   // (12 h-chunks, 23 d-pairs, 16 b)
    conv_mma_kernel<<<grid, TPB, smem_bytes>>>(x, bias);

    finalize_kernel<<<1, 512>>>(gn_w, gn_b, out);
}